// round 17
// baseline (speedup 1.0000x reference)
#include <cuda_runtime.h>
#include <cuda_fp16.h>
#include <cstdint>

#define BB 4
#define CK 64
#define NKEY 8192
#define MQ 1024
#define CVAL 512
#define BM 32
#define CHUNK 32
#define NCH (NKEY/CHUNK)   /* 256 */
#define NSTG 5
#define NT 384
#define SHIFT 10.0f

__device__ __half g_kth[(size_t)BB*NKEY*CK];   // [b][n][c] hi
__device__ __half g_qth[(size_t)BB*CK*MQ];     // [b][c][m] hi
__device__ __half g_qtl[(size_t)BB*CK*MQ];     // [b][c][m] lo
__device__ __half g_vhi[(size_t)BB*CVAL*NKEY]; // [b][c][n] hi
__device__ float  g_asq[BB*NKEY];
__device__ float  g_qsq[BB*MQ];

// smem byte offsets
#define SM_ASQ 0        /* 5 stages x 32 floats = 640 */
#define SM_QSQ 640      /* 32 floats */
#define SM_INV 768
#define SM_SE  896
#define SM_QH  1024     /* 64 rows x 80B */
#define SM_QL  6144
#define SM_P0  11264    /* 32 rows x 80B = 2560 */
#define SM_P1  13824
#define SM_KH  16384    /* 5 x 4096 */
#define SM_V   36864    /* 5 x 32768 */
#define SMEM_BYTES 200704

__device__ __forceinline__ uint32_t smem_u32(const void* p){
    uint32_t a;
    asm("{ .reg .u64 t; cvta.to.shared.u64 t, %1; cvt.u32.u64 %0, t; }":"=r"(a):"l"(p));
    return a;
}
__device__ __forceinline__ void cpa16(uint32_t s, const void* g){
    asm volatile("cp.async.cg.shared.global [%0], [%1], 16;"::"r"(s),"l"(g):"memory");
}
#define CP_COMMIT asm volatile("cp.async.commit_group;":::"memory")
#define CP_WAITN(n) asm volatile("cp.async.wait_group %0;"::"n"(n):"memory")
#define BARRIER   asm volatile("bar.sync 0, 384;":::"memory")

__device__ __forceinline__ uint32_t swz(uint32_t o){ return o ^ ((o>>3)&0x70); }     // 128B rows
__device__ __forceinline__ uint32_t swz64(uint32_t o){ return o ^ ((o>>3)&0x30); }   // 64B rows

__device__ __forceinline__ void ldsm4(uint32_t a, uint32_t* r){
    asm volatile("ldmatrix.sync.aligned.m8n8.x4.shared.b16 {%0,%1,%2,%3}, [%4];"
        :"=r"(r[0]),"=r"(r[1]),"=r"(r[2]),"=r"(r[3]):"r"(a));
}
__device__ __forceinline__ void ldsm4t(uint32_t a, uint32_t* r){
    asm volatile("ldmatrix.sync.aligned.m8n8.x4.trans.shared.b16 {%0,%1,%2,%3}, [%4];"
        :"=r"(r[0]),"=r"(r[1]),"=r"(r[2]),"=r"(r[3]):"r"(a));
}
__device__ __forceinline__ void mmaf16(float* d, const uint32_t* a, const uint32_t* b){
    asm volatile("mma.sync.aligned.m16n8k16.row.col.f32.f16.f16.f32 "
        "{%0,%1,%2,%3},{%4,%5,%6,%7},{%8,%9},{%0,%1,%2,%3};"
        :"+f"(d[0]),"+f"(d[1]),"+f"(d[2]),"+f"(d[3])
        :"r"(a[0]),"r"(a[1]),"r"(a[2]),"r"(a[3]),"r"(b[0]),"r"(b[1]));
}
// A-operand, 128B rows (K tile)
__device__ __forceinline__ uint32_t a_addr(uint32_t base, int rowbase, int kbyte, int lane){
    int r = rowbase + (lane&7) + ((lane>>3)&1)*8;
    uint32_t off = (uint32_t)(r*128 + kbyte + ((lane>>4)<<4));
    return base + swz(off);
}
// A-operand, 64B rows (V tile)
__device__ __forceinline__ uint32_t a_addr64(uint32_t base, int rowbase, int kbyte, int lane){
    int r = rowbase + (lane&7) + ((lane>>3)&1)*8;
    uint32_t off = (uint32_t)(r*64 + kbyte + ((lane>>4)<<4));
    return base + swz64(off);
}
// B-operand (row-major [k][n], 80B rows, trans)
__device__ __forceinline__ uint32_t b_addr(uint32_t base, int kbase, int nbase, int lane){
    int kk = kbase + (lane&7) + ((lane>>3)&1)*8;
    int nn = nbase + ((lane>>4)<<3);
    return base + (uint32_t)(kk*80 + nn*2);
}

// ---------------- fused prep: long-pole blocks FIRST ----------------
#define KP_BLKS 128
#define QS_BLKS 16
#define QP_BLKS 1024
#define VP_BLKS 16384
#define PREP_BLKS (KP_BLKS + QS_BLKS + QP_BLKS + VP_BLKS)

__global__ void prep(const float* __restrict__ mk, const float* __restrict__ qk,
                     const float* __restrict__ mv){
    int blk = blockIdx.x;
    if (blk < KP_BLKS){
        int i = blk*256 + threadIdx.x;
        int b = i>>13, n = i&(NKEY-1);
        const float* p = mk + ((size_t)b*CK)*NKEY + n;
        __half* oh = g_kth + ((size_t)b*NKEY + n)*CK;
        float s = 0.f;
#pragma unroll 8
        for (int c = 0; c < CK; ++c){
            float v = p[(size_t)c*NKEY];
            s = fmaf(v, v, s);
            oh[c] = __float2half_rn(v);
        }
        g_asq[i] = s;
        return;
    }
    blk -= KP_BLKS;
    if (blk < QS_BLKS){
        int i = blk*256 + threadIdx.x;
        int b = i>>10, m = i&(MQ-1);
        float s = 0.f;
#pragma unroll 8
        for (int c = 0; c < CK; ++c){ float v = qk[((size_t)b*CK+c)*MQ + m]; s = fmaf(v,v,s); }
        g_qsq[i] = s;
        return;
    }
    blk -= QS_BLKS;
    if (blk < QP_BLKS){
        int i = blk*256 + threadIdx.x;
        float v = qk[i];
        __half h = __float2half_rn(v);
        g_qth[i] = h; g_qtl[i] = __float2half_rn(v - __half2float(h));
        return;
    }
    blk -= QP_BLKS;
    {
        size_t base = ((size_t)blk*256 + threadIdx.x)*4;
        float4 v = *(const float4*)(mv + base);
        *(__half2*)(g_vhi+base)   = __halves2half2(__float2half_rn(v.x), __float2half_rn(v.y));
        *(__half2*)(g_vhi+base+2) = __halves2half2(__float2half_rn(v.z), __float2half_rn(v.w));
    }
}

// stage a full chunk (V + K + asq) into stage (stg). tid<256 only.
#define STAGE_CHUNK(n0, stg) do {                                               \
    if (tid < 256){                                                             \
        int c0s = tid>>2, sgv = tid&3;                                          \
        const __half* vp = g_vhi + ((size_t)b*CVAL + c0s)*NKEY + (n0) + sgv*8;  \
        uint32_t vb = sb + SM_V + (uint32_t)(stg)*32768u;                       \
        _Pragma("unroll")                                                       \
        for (int k2 = 0; k2 < 8; ++k2)                                          \
            cpa16(vb + swz64((uint32_t)((c0s + k2*64)*64 + sgv*16)),            \
                  vp + (size_t)k2*64*NKEY);                                     \
        int nk = tid>>3, sgk = tid&7;                                           \
        cpa16(sb + SM_KH + (uint32_t)(stg)*4096u + swz((uint32_t)(nk*128 + sgk*16)), \
              g_kth + ((size_t)b*NKEY + (n0) + nk)*CK + sgk*8);                 \
        if (tid < 8) cpa16(sb + SM_ASQ + (stg)*128 + tid*16,                    \
                           g_asq + b*NKEY + (n0) + tid*4);                      \
    }                                                                           \
    CP_COMMIT;                                                                  \
} while (0)

// QK: compute P(jj) into parity buffer, using K stage (stq)
#define QK_STEP(jj, stq) do {                                                   \
    const uint32_t KHb = sb + SM_KH + (uint32_t)(stq)*4096u;                    \
    const float* ASQb = smf + SM_ASQ/4 + (stq)*32;                              \
    float sacc[2][4] = {{0,0,0,0},{0,0,0,0}};                                   \
    _Pragma("unroll")                                                           \
    for (int ks = 0; ks < 4; ++ks){                                             \
        uint32_t ah[4];                                                         \
        ldsm4(a_addr(KHb, wn*16, ks*32, lane), ah);                             \
        mmaf16(sacc[0], ah, &qh[ks][0]); mmaf16(sacc[1], ah, &qh[ks][2]);       \
        mmaf16(sacc[0], ah, &ql[ks][0]); mmaf16(sacc[1], ah, &ql[ks][2]);       \
    }                                                                           \
    float as0 = ASQb[wn*16 + g]*0.125f, as1 = ASQb[wn*16 + g + 8]*0.125f;       \
    char* pb = smc + (((jj)&1) ? SM_P1 : SM_P0);                                \
    int r0 = (wn*16 + g)*80 + c0*2, r1 = r0 + 8*80;                             \
    float p00 = __expf(fmaf(sacc[0][0], 0.25f, qc[0] - as0));                   \
    float p01 = __expf(fmaf(sacc[0][1], 0.25f, qc[1] - as0));                   \
    float p10 = __expf(fmaf(sacc[0][2], 0.25f, qc[0] - as1));                   \
    float p11 = __expf(fmaf(sacc[0][3], 0.25f, qc[1] - as1));                   \
    se[0] += p00 + p10; se[1] += p01 + p11;                                     \
    *(__half2*)(pb + r0) = __halves2half2(__float2half_rn(p00), __float2half_rn(p01)); \
    *(__half2*)(pb + r1) = __halves2half2(__float2half_rn(p10), __float2half_rn(p11)); \
    p00 = __expf(fmaf(sacc[1][0], 0.25f, qc[2] - as0));                         \
    p01 = __expf(fmaf(sacc[1][1], 0.25f, qc[3] - as0));                         \
    p10 = __expf(fmaf(sacc[1][2], 0.25f, qc[2] - as1));                         \
    p11 = __expf(fmaf(sacc[1][3], 0.25f, qc[3] - as1));                         \
    se[2] += p00 + p10; se[3] += p01 + p11;                                     \
    *(__half2*)(pb + r0 + 16) = __halves2half2(__float2half_rn(p00), __float2half_rn(p01)); \
    *(__half2*)(pb + r1 + 16) = __halves2half2(__float2half_rn(p10), __float2half_rn(p11)); \
} while (0)

__global__ void __launch_bounds__(NT,1) mr_hmma(float* __restrict__ out){
    extern __shared__ char smc[];
    float* smf = (float*)smc;
    const uint32_t sb = smem_u32(smc);
    const int tid = threadIdx.x, wid = tid>>5, lane = tid&31;
    const int b = blockIdx.y, m0 = blockIdx.x*BM;
    const int g = lane>>2, tg = lane&3;

    if (tid < 32) smf[SM_SE/4 + tid] = 0.f;
    // ---- prologue: G0 = Q + qsq + chunk0; G1..G3 = chunks 1..3 ----
    if (tid < 256){
        int c = tid>>2, sg4 = tid&3;
        size_t qo = ((size_t)b*CK + c)*MQ + m0 + sg4*8;
        cpa16(sb + SM_QH + c*80 + sg4*16, g_qth + qo);
        cpa16(sb + SM_QL + c*80 + sg4*16, g_qtl + qo);
        if (tid < 8) cpa16(sb + SM_QSQ + tid*16, g_qsq + b*MQ + m0 + tid*4);
    }
    STAGE_CHUNK(0, 0);
    STAGE_CHUNK(1*CHUNK, 1);
    STAGE_CHUNK(2*CHUNK, 2);
    STAGE_CHUNK(3*CHUNK, 3);

    if (wid < 8){
        // ========== PV branch (warps 0-7, 64 c-rows each) ==========
        float pacc[4][4][4];
#pragma unroll
        for (int i = 0; i < 4; ++i)
#pragma unroll
            for (int j2 = 0; j2 < 4; ++j2)
#pragma unroll
                for (int k = 0; k < 4; ++k) pacc[i][j2][k] = 0.f;

        CP_WAITN(3); BARRIER;       // G0 done (QK computes P_0 now)
        CP_WAITN(2); BARRIER;       // G1 done (K1 ready)

        int st = 0;                 // stage of chunk j
        for (int j = 0; j < NCH; ++j){
            // prefetch chunk j+4 into stage (j+4)%5 == (st+4)%5
            if (j + 4 < NCH){
                int stp = (st >= 1) ? st - 1 : 4;   // (st+4)%5
                STAGE_CHUNK((j+4)*CHUNK, stp);
            } else { CP_COMMIT; }

            const uint32_t Vst = sb + SM_V + (uint32_t)st*32768u;
            const uint32_t Pb = sb + ((j&1) ? SM_P1 : SM_P0);
#pragma unroll
            for (int ks = 0; ks < 2; ++ks){
                uint32_t va[4][4], bh[2][4];
#pragma unroll
                for (int ct = 0; ct < 4; ++ct)
                    ldsm4(a_addr64(Vst, wid*64 + ct*16, ks*32, lane), va[ct]);
#pragma unroll
                for (int mh = 0; mh < 2; ++mh)
                    ldsm4t(b_addr(Pb, ks*16, mh*16, lane), bh[mh]);
#pragma unroll
                for (int ct = 0; ct < 4; ++ct)
#pragma unroll
                    for (int mt = 0; mt < 4; ++mt)
                        mmaf16(pacc[ct][mt], va[ct], &bh[mt>>1][(mt&1)*2]);
            }
            st = (st == 4) ? 0 : st + 1;
            CP_WAITN(2);            // chunk j+2 complete
            BARRIER;
        }
        BARRIER;                    // SE atomics complete
        if (tid < 32) smf[SM_INV/4 + tid] = 1.f / smf[SM_SE/4 + tid];
        BARRIER;
        // writeout
#pragma unroll
        for (int ct = 0; ct < 4; ++ct){
            int c = wid*64 + ct*16 + g;
            float* po0 = out + ((size_t)(b*CVAL + c))*MQ + m0;
            float* po1 = po0 + 8*MQ;
#pragma unroll
            for (int mt = 0; mt < 4; ++mt){
                int m = mt*8 + tg*2;
                float i0 = smf[SM_INV/4 + m], i1 = smf[SM_INV/4 + m + 1];
                float2 o0 = { pacc[ct][mt][0]*i0, pacc[ct][mt][1]*i1 };
                float2 o1 = { pacc[ct][mt][2]*i0, pacc[ct][mt][3]*i1 };
                *(float2*)(po0 + m) = o0;
                *(float2*)(po1 + m) = o1;
            }
        }
    } else {
        // ========== QK branch (warps 8-11 active, 4 jobs) ==========
        const int qw = wid - 8, wn = qw&1, wm8 = qw>>1;
        CP_WAITN(3); BARRIER;
        uint32_t qh[4][4], ql[4][4];
        float qc[4];
        float se[4] = {0.f, 0.f, 0.f, 0.f};
        const int c0 = wm8*16 + tg*2;
        {
#pragma unroll
            for (int ks = 0; ks < 4; ++ks){
                ldsm4t(b_addr(sb + SM_QH, ks*16, wm8*16, lane), qh[ks]);
                ldsm4t(b_addr(sb + SM_QL, ks*16, wm8*16, lane), ql[ks]);
            }
            qc[0] = -smf[SM_QSQ/4 + c0]    *0.125f + SHIFT;
            qc[1] = -smf[SM_QSQ/4 + c0 + 1]*0.125f + SHIFT;
            qc[2] = -smf[SM_QSQ/4 + c0 + 8]*0.125f + SHIFT;
            qc[3] = -smf[SM_QSQ/4 + c0 + 9]*0.125f + SHIFT;
            QK_STEP(0, 0);          // P_0 into buf 0
        }
        CP_WAITN(2); BARRIER;

        int stq = 1;                // stage of chunk j+1
        for (int j = 0; j < NCH; ++j){
            if (j + 1 < NCH) QK_STEP(j + 1, stq);
            stq = (stq == 4) ? 0 : stq + 1;
            BARRIER;
        }
        // sumexp reduce + publish
#pragma unroll
        for (int cc = 0; cc < 4; ++cc){
            float v = se[cc];
            v += __shfl_xor_sync(0xffffffffu, v, 4);
            v += __shfl_xor_sync(0xffffffffu, v, 8);
            v += __shfl_xor_sync(0xffffffffu, v, 16);
            if (g == 0) atomicAdd(smf + SM_SE/4 + c0 + (cc&1) + (cc>>1)*8, v);
        }
        BARRIER;                    // publish SE
        BARRIER;                    // INV computed by PV side
    }
}

extern "C" void kernel_launch(void* const* d_in, const int* in_sizes, int n_in,
                              void* d_out, int out_size){
    const float* mk = (const float*)d_in[0];
    const float* qk = (const float*)d_in[1];
    const float* mv = (const float*)d_in[2];
    float* out = (float*)d_out;

    prep<<<PREP_BLKS, 256>>>(mk, qk, mv);

    cudaFuncSetAttribute(mr_hmma, cudaFuncAttributeMaxDynamicSharedMemorySize, SMEM_BYTES);
    dim3 grid(MQ/BM, BB);
    mr_hmma<<<grid, NT, SMEM_BYTES>>>(out);
}